// round 11
// baseline (speedup 1.0000x reference)
#include <cuda_runtime.h>

// out[b] = sum_j exp(-K2_j) * K2_j / sum_j exp(-K2_j),
// K2_j = (x_j - mean(x))^2 over all_atom_features of batch b.
// (softmax_j over -(Q2_i + K2_j) cancels Q2_i exactly -> cdr3 input unused.
//  K2 >= 0 so exp(-K2) <= 1: no max-shift needed for fp32 safety.)
//
// Latency/overhead-bound regime (grid=4, all pipes <0.5%). Empirical best
// config across R2-R10: 8 warps/block, 32 elems/thread in registers, MLP=8
// front-batched LDG.128, 2 barriers. Measured: 1024thr=6.18us, 128thr=5.02us,
// 256thr=4.64us (ncu). Remaining time is launch ramp + graph replay overhead.

#define M 8192
#define NTHREADS 256
#define NWARPS (NTHREADS / 32)   // 8
#define VECS  8                  // float4 loads per thread (32 elems)

__global__ __launch_bounds__(NTHREADS)
void invariant_cross_attention_kernel(const float4* __restrict__ atom4,
                                      float* __restrict__ out) {
    __shared__ float  red1[NWARPS];
    __shared__ float2 red2[NWARPS];

    const int tid  = threadIdx.x;
    const int lane = tid & 31;
    const int wid  = tid >> 5;
    const float4* __restrict__ x4 = atom4 + (size_t)blockIdx.x * (M / 4);

    // ---- Front-batched loads: 8x LDG.128 in flight (MLP=8) ----
    float4 v[VECS];
    #pragma unroll
    for (int k = 0; k < VECS; k++) v[k] = x4[tid + k * NTHREADS];

    // ---- Reduction 1: sum -> mean (pairwise tree inside thread) ----
    float sum;
    {
        float p0 = 0.0f, p1 = 0.0f;
        #pragma unroll
        for (int k = 0; k < VECS; k += 2) {
            p0 += ((v[k].x + v[k].y) + (v[k].z + v[k].w));
            p1 += ((v[k+1].x + v[k+1].y) + (v[k+1].z + v[k+1].w));
        }
        sum = p0 + p1;
    }
    #pragma unroll
    for (int o = 16; o > 0; o >>= 1) sum += __shfl_down_sync(0xffffffffu, sum, o);
    if (lane == 0) red1[wid] = sum;
    __syncthreads();
    // Replicated load + xor-butterfly: every lane reads one of the 8 partials
    // (lane&7) and 3 xor steps leave the full total in ALL lanes -> no
    // broadcast shfl on the critical path.
    float total = red1[lane & 7];
    total += __shfl_xor_sync(0xffffffffu, total, 4);
    total += __shfl_xor_sync(0xffffffffu, total, 2);
    total += __shfl_xor_sync(0xffffffffu, total, 1);
    const float mean = total * (1.0f / (float)M);

    // ---- Pass 2 (registers only): s = sum exp(-k2), num = sum exp(-k2)*k2 ----
    // Dual accumulators to shorten FFMA dependency chains behind MUFU results.
    float s0 = 0.0f, s1 = 0.0f, n0 = 0.0f, n1 = 0.0f;
    #pragma unroll
    for (int k = 0; k < VECS; k++) {
        float d0 = v[k].x - mean, d1 = v[k].y - mean,
              d2 = v[k].z - mean, d3 = v[k].w - mean;
        float a = d0 * d0, b = d1 * d1, c = d2 * d2, dd = d3 * d3;
        float e0 = __expf(-a), e1 = __expf(-b), e2 = __expf(-c), e3 = __expf(-dd);
        s0 += (e0 + e1);
        s1 += (e2 + e3);
        n0 = fmaf(e0, a, n0); n1 = fmaf(e1, b, n1);
        n0 = fmaf(e2, c, n0); n1 = fmaf(e3, dd, n1);
    }
    float s = s0 + s1, num = n0 + n1;

    // ---- Reduction 2: joint (s, num) ----
    #pragma unroll
    for (int o = 16; o > 0; o >>= 1) {
        s   += __shfl_down_sync(0xffffffffu, s, o);
        num += __shfl_down_sync(0xffffffffu, num, o);
    }
    if (lane == 0) red2[wid] = make_float2(s, num);
    __syncthreads();
    if (wid == 0 && lane < NWARPS) {
        float2 t = red2[lane];
        t.x += __shfl_down_sync(0xffffffffu, t.x, 4);
        t.y += __shfl_down_sync(0xffffffffu, t.y, 4);
        t.x += __shfl_down_sync(0xffffffffu, t.x, 2);
        t.y += __shfl_down_sync(0xffffffffu, t.y, 2);
        t.x += __shfl_down_sync(0xffffffffu, t.x, 1);
        t.y += __shfl_down_sync(0xffffffffu, t.y, 1);
        if (lane == 0) out[blockIdx.x] = t.y / t.x;
    }
}

extern "C" void kernel_launch(void* const* d_in, const int* in_sizes, int n_in,
                              void* d_out, int out_size) {
    // d_in[0] = cdr3_features  [4, 2048, 1] (mathematically irrelevant; unused)
    // d_in[1] = all_atom_features [4, 8192, 1]
    const float4* atom4 = (const float4*)d_in[1];
    float* out = (float*)d_out;
    const int B = in_sizes[1] / M;   // 4
    invariant_cross_attention_kernel<<<B, NTHREADS>>>(atom4, out);
}

// round 12
// speedup vs baseline: 1.0435x; 1.0435x over previous
#include <cuda_runtime.h>

// out[b] = sum_j exp(-K2_j) * K2_j / sum_j exp(-K2_j),
// K2_j = (x_j - mean(x))^2 over all_atom_features of batch b.
// (softmax_j over -(Q2_i + K2_j) cancels Q2_i exactly -> cdr3 input unused.
//  K2 >= 0 so exp(-K2) <= 1: no max-shift needed for fp32 safety.)
//
// Algebraic trim: with C = sqrt(log2 e), t = (x-mu)*C:
//   exp(-(x-mu)^2) = 2^(-t^2) = EX2(-t*t)     (1 FFMA + 1 FMUL + 1 MUFU)
//   sum e*K2 = ln2 * sum e*t^2                 (recovered off-loop)
//
// Launch/overhead-bound regime (grid=4, all pipes <0.5%; ncu kernel time
// varies +-1.5us on identical code due to clock-control none). Best config:
// 8 warps/block, 32 elems/thread in regs, MLP=8 LDG.128, 2 barriers.

#define M 8192
#define NTHREADS 256
#define NWARPS (NTHREADS / 32)   // 8
#define VECS  8                  // float4 loads per thread (32 elems)

__device__ __forceinline__ float ex2_approx(float a) {
    float r;
    asm("ex2.approx.f32 %0, %1;" : "=f"(r) : "f"(a));
    return r;
}

__global__ __launch_bounds__(NTHREADS)
void invariant_cross_attention_kernel(const float4* __restrict__ atom4,
                                      float* __restrict__ out) {
    __shared__ float  red1[NWARPS];
    __shared__ float2 red2[NWARPS];

    const int tid  = threadIdx.x;
    const int lane = tid & 31;
    const int wid  = tid >> 5;
    const float4* __restrict__ x4 = atom4 + (size_t)blockIdx.x * (M / 4);

    // ---- Front-batched loads: 8x LDG.128 in flight (MLP=8) ----
    float4 v[VECS];
    #pragma unroll
    for (int k = 0; k < VECS; k++) v[k] = x4[tid + k * NTHREADS];

    // ---- Reduction 1: sum -> mean (pairwise tree inside thread) ----
    float sum;
    {
        float p0 = 0.0f, p1 = 0.0f;
        #pragma unroll
        for (int k = 0; k < VECS; k += 2) {
            p0 += ((v[k].x + v[k].y) + (v[k].z + v[k].w));
            p1 += ((v[k+1].x + v[k+1].y) + (v[k+1].z + v[k+1].w));
        }
        sum = p0 + p1;
    }
    #pragma unroll
    for (int o = 16; o > 0; o >>= 1) sum += __shfl_down_sync(0xffffffffu, sum, o);
    if (lane == 0) red1[wid] = sum;
    __syncthreads();
    // Replicated load + xor-butterfly: total lands in every lane, no broadcast.
    float total = red1[lane & 7];
    total += __shfl_xor_sync(0xffffffffu, total, 4);
    total += __shfl_xor_sync(0xffffffffu, total, 2);
    total += __shfl_xor_sync(0xffffffffu, total, 1);
    const float mean = total * (1.0f / (float)M);

    // ---- Pass 2 (registers only) ----
    // t = x*C - mean*C; a = t*t; e = EX2(-a); s += e; n = fma(e, a, n)
    const float C     = 1.2011224087864498f;   // sqrt(log2(e))
    const float negMC = -mean * C;
    float s0 = 0.0f, s1 = 0.0f, n0 = 0.0f, n1 = 0.0f;
    #pragma unroll
    for (int k = 0; k < VECS; k++) {
        float t0 = fmaf(v[k].x, C, negMC);
        float t1 = fmaf(v[k].y, C, negMC);
        float t2 = fmaf(v[k].z, C, negMC);
        float t3 = fmaf(v[k].w, C, negMC);
        float a0 = t0 * t0, a1 = t1 * t1, a2 = t2 * t2, a3 = t3 * t3;
        float e0 = ex2_approx(-a0), e1 = ex2_approx(-a1),
              e2 = ex2_approx(-a2), e3 = ex2_approx(-a3);
        s0 += (e0 + e1);
        s1 += (e2 + e3);
        n0 = fmaf(e0, a0, n0); n1 = fmaf(e1, a1, n1);
        n0 = fmaf(e2, a2, n0); n1 = fmaf(e3, a3, n1);
    }
    float s = s0 + s1, num = n0 + n1;   // num is in t^2 units; scale at the end

    // ---- Reduction 2: joint (s, num) ----
    #pragma unroll
    for (int o = 16; o > 0; o >>= 1) {
        s   += __shfl_down_sync(0xffffffffu, s, o);
        num += __shfl_down_sync(0xffffffffu, num, o);
    }
    if (lane == 0) red2[wid] = make_float2(s, num);
    __syncthreads();
    if (wid == 0 && lane < NWARPS) {
        float2 t = red2[lane];
        t.x += __shfl_down_sync(0xffffffffu, t.x, 4);
        t.y += __shfl_down_sync(0xffffffffu, t.y, 4);
        t.x += __shfl_down_sync(0xffffffffu, t.x, 2);
        t.y += __shfl_down_sync(0xffffffffu, t.y, 2);
        t.x += __shfl_down_sync(0xffffffffu, t.x, 1);
        t.y += __shfl_down_sync(0xffffffffu, t.y, 1);
        if (lane == 0)
            out[blockIdx.x] = (t.y * 0.6931471805599453f) / t.x;  // * ln2
    }
}

extern "C" void kernel_launch(void* const* d_in, const int* in_sizes, int n_in,
                              void* d_out, int out_size) {
    // d_in[0] = cdr3_features  [4, 2048, 1] (mathematically irrelevant; unused)
    // d_in[1] = all_atom_features [4, 8192, 1]
    const float4* atom4 = (const float4*)d_in[1];
    float* out = (float*)d_out;
    const int B = in_sizes[1] / M;   // 4
    invariant_cross_attention_kernel<<<B, NTHREADS>>>(atom4, out);
}

// round 14
// speedup vs baseline: 1.0800x; 1.0350x over previous
#include <cuda_runtime.h>

// out[b] = sum_j exp(-K2_j) * K2_j / sum_j exp(-K2_j),
// K2_j = (x_j - mean(x))^2 over all_atom_features of batch b.
// (softmax_j over -(Q2_i + K2_j) cancels Q2_i exactly -> cdr3 input unused.
//  K2 >= 0 so exp(-K2) <= 1: no max-shift needed for fp32 safety.)
//
// Algebraic trim: with C = sqrt(log2 e), t = (x-mu)*C:
//   exp(-(x-mu)^2) = 2^(-t^2) = EX2(-t*t)     (1 FFMA + 1 FMUL + 1 MUFU)
//   sum e*K2 = ln2 * sum e*t^2                 (recovered off-loop)
//
// Launch/overhead-bound regime (grid=4, all pipes <0.5%): measured floor is
// bench ~6.6us = ~0.6us critical path + ~4us grid ramp/drain + ~2us graph
// replay. Best config: 8 warps/block, 32 elems/thread in regs, MLP=8
// front-batched LDG.128, 2 barriers. Confirmed stable across 7 benches.

#define M 8192
#define NTHREADS 256
#define NWARPS (NTHREADS / 32)   // 8
#define VECS  8                  // float4 loads per thread (32 elems)

__device__ __forceinline__ float ex2_approx(float a) {
    float r;
    asm("ex2.approx.f32 %0, %1;" : "=f"(r) : "f"(a));
    return r;
}

__global__ __launch_bounds__(NTHREADS)
void invariant_cross_attention_kernel(const float4* __restrict__ atom4,
                                      float* __restrict__ out) {
    __shared__ float  red1[NWARPS];
    __shared__ float2 red2[NWARPS];

    const int tid  = threadIdx.x;
    const int lane = tid & 31;
    const int wid  = tid >> 5;
    const float4* __restrict__ x4 = atom4 + (size_t)blockIdx.x * (M / 4);

    // ---- Front-batched loads: 8x LDG.128 in flight (MLP=8) ----
    float4 v[VECS];
    #pragma unroll
    for (int k = 0; k < VECS; k++) v[k] = x4[tid + k * NTHREADS];

    // ---- Reduction 1: sum -> mean (pairwise tree inside thread) ----
    float sum;
    {
        float p0 = 0.0f, p1 = 0.0f;
        #pragma unroll
        for (int k = 0; k < VECS; k += 2) {
            p0 += ((v[k].x + v[k].y) + (v[k].z + v[k].w));
            p1 += ((v[k+1].x + v[k+1].y) + (v[k+1].z + v[k+1].w));
        }
        sum = p0 + p1;
    }
    #pragma unroll
    for (int o = 16; o > 0; o >>= 1) sum += __shfl_down_sync(0xffffffffu, sum, o);
    if (lane == 0) red1[wid] = sum;
    __syncthreads();
    // Replicated load + xor-butterfly: total lands in every lane, no broadcast.
    float total = red1[lane & 7];
    total += __shfl_xor_sync(0xffffffffu, total, 4);
    total += __shfl_xor_sync(0xffffffffu, total, 2);
    total += __shfl_xor_sync(0xffffffffu, total, 1);
    const float mean = total * (1.0f / (float)M);

    // ---- Pass 2 (registers only) ----
    // t = x*C - mean*C; a = t*t; e = EX2(-a); s += e; n = fma(e, a, n)
    const float C     = 1.2011224087864498f;   // sqrt(log2(e))
    const float negMC = -mean * C;
    float s0 = 0.0f, s1 = 0.0f, n0 = 0.0f, n1 = 0.0f;
    #pragma unroll
    for (int k = 0; k < VECS; k++) {
        float t0 = fmaf(v[k].x, C, negMC);
        float t1 = fmaf(v[k].y, C, negMC);
        float t2 = fmaf(v[k].z, C, negMC);
        float t3 = fmaf(v[k].w, C, negMC);
        float a0 = t0 * t0, a1 = t1 * t1, a2 = t2 * t2, a3 = t3 * t3;
        float e0 = ex2_approx(-a0), e1 = ex2_approx(-a1),
              e2 = ex2_approx(-a2), e3 = ex2_approx(-a3);
        s0 += (e0 + e1);
        s1 += (e2 + e3);
        n0 = fmaf(e0, a0, n0); n1 = fmaf(e1, a1, n1);
        n0 = fmaf(e2, a2, n0); n1 = fmaf(e3, a3, n1);
    }
    float s = s0 + s1, num = n0 + n1;   // num in t^2 units; scale by ln2 at end

    // ---- Reduction 2: joint (s, num), same butterfly pattern ----
    #pragma unroll
    for (int o = 16; o > 0; o >>= 1) {
        s   += __shfl_down_sync(0xffffffffu, s, o);
        num += __shfl_down_sync(0xffffffffu, num, o);
    }
    if (lane == 0) red2[wid] = make_float2(s, num);
    __syncthreads();
    // All warps redundantly reduce the 8 partials (no divergent wid==0 tail);
    // tid 0 stores as soon as its butterfly completes.
    {
        float2 t = red2[lane & 7];
        t.x += __shfl_xor_sync(0xffffffffu, t.x, 4);
        t.y += __shfl_xor_sync(0xffffffffu, t.y, 4);
        t.x += __shfl_xor_sync(0xffffffffu, t.x, 2);
        t.y += __shfl_xor_sync(0xffffffffu, t.y, 2);
        t.x += __shfl_xor_sync(0xffffffffu, t.x, 1);
        t.y += __shfl_xor_sync(0xffffffffu, t.y, 1);
        if (tid == 0)
            out[blockIdx.x] = (t.y * 0.6931471805599453f) / t.x;  // * ln2
    }
}

extern "C" void kernel_launch(void* const* d_in, const int* in_sizes, int n_in,
                              void* d_out, int out_size) {
    // d_in[0] = cdr3_features  [4, 2048, 1] (mathematically irrelevant; unused)
    // d_in[1] = all_atom_features [4, 8192, 1]
    const float4* atom4 = (const float4*)d_in[1];
    float* out = (float*)d_out;
    const int B = in_sizes[1] / M;   // 4
    invariant_cross_attention_kernel<<<B, NTHREADS>>>(atom4, out);
}